// round 1
// baseline (speedup 1.0000x reference)
#include <cuda_runtime.h>
#include <cuda_bf16.h>

// FinDiffNonUniform: yd[i,b] = sum_s w[i,s] * y[i + off[i,s], b]
// N=8192 rows, B=4096 cols, S=7 stencil.
//
// Strategy: register sliding window over rows. Each thread owns 4 columns
// (float4) and TR=8 consecutive rows. Interior tiles (verified at runtime)
// have offsets exactly s-3, so the 14-row window [i0-3, i0+10) covers all
// gathers with COMPILE-TIME indices -> pure register reuse, 1.75 y-reads
// per output instead of 7. Boundary / mismatching tiles take a generic
// global-gather path (correct for any offsets produced by _make_offsets,
// whose reach is always within the clamped window anyway).

#define S_W 7
#define TR 8
#define TPB 256
#define VEC 4
#define COLS_PER_BLOCK (TPB * VEC)

__global__ __launch_bounds__(TPB)
void findiff_vec_kernel(const float* __restrict__ y,
                        const float* __restrict__ coef,
                        const int* __restrict__ offs,
                        float* __restrict__ out,
                        int N, int B)
{
    __shared__ float s_w[TR * S_W];
    __shared__ int   s_o[TR * S_W];
    __shared__ int   s_centered;   // 1 if this tile's offsets are exactly s-3

    const int t  = threadIdx.x;
    const int i0 = blockIdx.y * TR;

    if (t == 0) s_centered = 1;
    __syncthreads();

    if (t < TR * S_W) {
        int gidx = i0 * S_W + t;
        if (gidx < N * S_W) {
            s_w[t] = coef[gidx];
            int o  = offs[gidx];
            s_o[t] = o;
            if (o != (t % S_W) - 3) s_centered = 0;
        } else {
            s_w[t] = 0.0f;
            s_o[t] = 0;
        }
    }
    __syncthreads();

    const int col = blockIdx.x * COLS_PER_BLOCK + t * VEC;
    if (col + VEC - 1 >= B + (VEC - 1)) return;   // (B multiple of VEC enforced at launch)
    if (col >= B) return;

    const bool interior = (i0 >= 3) && (i0 + TR + 2 <= N - 1) && s_centered;

    if (interior) {
        // ---- fast path: register sliding window, static offsets s-3 ----
        float4 win[TR + 6];
        const float* base = y + (size_t)(i0 - 3) * (size_t)B + col;
        #pragma unroll
        for (int k = 0; k < TR + 6; ++k)
            win[k] = *reinterpret_cast<const float4*>(base + (size_t)k * (size_t)B);

        #pragma unroll
        for (int r = 0; r < TR; ++r) {
            float4 acc = make_float4(0.f, 0.f, 0.f, 0.f);
            #pragma unroll
            for (int s = 0; s < S_W; ++s) {
                const float w = s_w[r * S_W + s];
                const float4 v = win[r + s];
                acc.x = fmaf(w, v.x, acc.x);
                acc.y = fmaf(w, v.y, acc.y);
                acc.z = fmaf(w, v.z, acc.z);
                acc.w = fmaf(w, v.w, acc.w);
            }
            *reinterpret_cast<float4*>(out + (size_t)(i0 + r) * (size_t)B + col) = acc;
        }
    } else {
        // ---- generic path: per-row gather from global (boundary tiles) ----
        #pragma unroll
        for (int r = 0; r < TR; ++r) {
            const int i = i0 + r;
            if (i >= N) break;
            float4 acc = make_float4(0.f, 0.f, 0.f, 0.f);
            #pragma unroll
            for (int s = 0; s < S_W; ++s) {
                const float w = s_w[r * S_W + s];
                const int   j = i + s_o[r * S_W + s];
                const float4 v = *reinterpret_cast<const float4*>(
                    y + (size_t)j * (size_t)B + col);
                acc.x = fmaf(w, v.x, acc.x);
                acc.y = fmaf(w, v.y, acc.y);
                acc.z = fmaf(w, v.z, acc.z);
                acc.w = fmaf(w, v.w, acc.w);
            }
            *reinterpret_cast<float4*>(out + (size_t)i * (size_t)B + col) = acc;
        }
    }
}

// Fully generic scalar fallback (any N, B, including B not divisible by 4).
__global__ void findiff_scalar_kernel(const float* __restrict__ y,
                                      const float* __restrict__ coef,
                                      const int* __restrict__ offs,
                                      float* __restrict__ out,
                                      int N, int B)
{
    const long long total = (long long)N * B;
    for (long long idx = (long long)blockIdx.x * blockDim.x + threadIdx.x;
         idx < total;
         idx += (long long)gridDim.x * blockDim.x) {
        const int i = (int)(idx / B);
        const int b = (int)(idx % B);
        float acc = 0.f;
        #pragma unroll
        for (int s = 0; s < S_W; ++s) {
            const float w = coef[i * S_W + s];
            const int   j = i + offs[i * S_W + s];
            acc = fmaf(w, y[(size_t)j * (size_t)B + b], acc);
        }
        out[idx] = acc;
    }
}

extern "C" void kernel_launch(void* const* d_in, const int* in_sizes, int n_in,
                              void* d_out, int out_size)
{
    const float* y    = (const float*)d_in[0];
    const float* coef = (const float*)d_in[1];
    const int*   offs = (const int*)d_in[2];
    float* out = (float*)d_out;

    const int N = in_sizes[1] / S_W;       // all_coefficients is [N, 7]
    const int B = in_sizes[0] / N;         // y is [N, B]

    if ((B % VEC) == 0 && (B % COLS_PER_BLOCK) == 0) {
        dim3 grid(B / COLS_PER_BLOCK, (N + TR - 1) / TR);
        findiff_vec_kernel<<<grid, TPB>>>(y, coef, offs, out, N, B);
    } else {
        const long long total = (long long)N * B;
        int blocks = (int)((total + 255) / 256);
        if (blocks > 65535 * 32) blocks = 65535 * 32;
        findiff_scalar_kernel<<<blocks, 256>>>(y, coef, offs, out, N, B);
    }
}